// round 12
// baseline (speedup 1.0000x reference)
#include <cuda_runtime.h>
#include <cuda_fp16.h>
#include <math_constants.h>
#include <cstdint>

#define T 2048
#define D 1024
#define H 16
#define DH 64
#define D3 3072
#define D2 2048
#define DFF 4096
#define LN_EPS 1e-5f
#define SPARSITY_LAMBDA 0.0005f

// ---------------- scratch ----------------
__device__ __half g_xnh[(size_t)T * D];
__device__ __half g_qkvh[(size_t)T * D3];
__device__ __half g_cath[(size_t)T * D2];
__device__ __half g_tmph[(size_t)T * D];
__device__ float  g_h[(size_t)T * D];
__device__ __half g_hnh[(size_t)T * D];
__device__ __half g_ffh[(size_t)T * DFF];
__device__ __half g_wqkvh[(size_t)D3 * D];
__device__ __half g_wgateh[(size_t)D * D2];
__device__ __half g_wouth[(size_t)D * D];
__device__ __half g_wff1h[(size_t)DFF * D];
__device__ __half g_wff2h[(size_t)D * DFF];
__device__ double g_sigacc;

// ---------------- helpers ----------------
__device__ __forceinline__ void mma_f16(float (&d)[4], const uint32_t (&a)[4], const uint32_t (&b)[2]) {
    asm volatile(
        "mma.sync.aligned.m16n8k16.row.col.f32.f16.f16.f32 "
        "{%0,%1,%2,%3}, {%4,%5,%6,%7}, {%8,%9}, {%0,%1,%2,%3};\n"
        : "+f"(d[0]), "+f"(d[1]), "+f"(d[2]), "+f"(d[3])
        : "r"(a[0]), "r"(a[1]), "r"(a[2]), "r"(a[3]), "r"(b[0]), "r"(b[1]));
}

__device__ __forceinline__ void ldsm_x4(uint32_t& r0, uint32_t& r1, uint32_t& r2, uint32_t& r3,
                                        const void* sptr) {
    uint32_t addr = (uint32_t)__cvta_generic_to_shared(sptr);
    asm volatile("ldmatrix.sync.aligned.m8n8.x4.shared.b16 {%0,%1,%2,%3}, [%4];"
                 : "=r"(r0), "=r"(r1), "=r"(r2), "=r"(r3) : "r"(addr));
}

__device__ __forceinline__ void cp16(void* sdst, const void* gsrc) {
    uint32_t s = (uint32_t)__cvta_generic_to_shared(sdst);
    asm volatile("cp.async.cg.shared.global [%0], [%1], 16;" :: "r"(s), "l"(gsrc));
}
__device__ __forceinline__ void cp_commit() { asm volatile("cp.async.commit_group;"); }
template<int N> __device__ __forceinline__ void cp_wait() {
    asm volatile("cp.async.wait_group %0;" :: "n"(N));
}

__device__ __forceinline__ float sigf(float x) { return 1.f / (1.f + __expf(-x)); }

__device__ __forceinline__ float blockReduceSum(float v) {
    __shared__ float red[32];
    int lane = threadIdx.x & 31, wid = threadIdx.x >> 5;
    #pragma unroll
    for (int o = 16; o > 0; o >>= 1) v += __shfl_xor_sync(0xffffffff, v, o);
    __syncthreads();
    if (lane == 0) red[wid] = v;
    __syncthreads();
    int nw = (blockDim.x + 31) >> 5;
    float r = (threadIdx.x < nw) ? red[threadIdx.x] : 0.f;
    if (wid == 0) {
        #pragma unroll
        for (int o = 16; o > 0; o >>= 1) r += __shfl_xor_sync(0xffffffff, r, o);
        if (lane == 0) red[0] = r;
    }
    __syncthreads();
    return red[0];
}

// ---------------- merged fp32 -> fp16 conversion for all 5 weights ----------------
#define N4_QKV  786432
#define N4_GATE 524288
#define N4_OUT  262144
#define N4_FF1  1048576
#define N4_FF2  1048576
#define N4_TOT  (N4_QKV + N4_GATE + N4_OUT + N4_FF1 + N4_FF2)

__global__ __launch_bounds__(256) void k_f2h_all(
    const float* __restrict__ wqkv, const float* __restrict__ wgate,
    const float* __restrict__ wout, const float* __restrict__ wff1,
    const float* __restrict__ wff2,
    __half* __restrict__ hqkv, __half* __restrict__ hgate,
    __half* __restrict__ hout, __half* __restrict__ hff1,
    __half* __restrict__ hff2)
{
    for (int i = blockIdx.x * 256 + threadIdx.x; i < N4_TOT; i += gridDim.x * 256) {
        const float* src; __half* dst; int off;
        if (i < N4_QKV)                         { src = wqkv;  dst = hqkv;  off = i; }
        else if (i < N4_QKV + N4_GATE)          { src = wgate; dst = hgate; off = i - N4_QKV; }
        else if (i < N4_QKV + N4_GATE + N4_OUT) { src = wout;  dst = hout;  off = i - N4_QKV - N4_GATE; }
        else if (i < N4_QKV + N4_GATE + N4_OUT + N4_FF1)
                                                { src = wff1;  dst = hff1;  off = i - N4_QKV - N4_GATE - N4_OUT; }
        else                                    { src = wff2;  dst = hff2;  off = i - N4_QKV - N4_GATE - N4_OUT - N4_FF1; }
        float4 v = *(const float4*)(src + (size_t)off * 4);
        __half2* o = (__half2*)(dst + (size_t)off * 4);
        o[0] = __floats2half2_rn(v.x, v.y);
        o[1] = __floats2half2_rn(v.z, v.w);
    }
}

// ---------------- layernorm (half output) ----------------
__global__ __launch_bounds__(256) void k_layernorm_h(
    const float* __restrict__ x, const float* __restrict__ g,
    const float* __restrict__ b, __half* __restrict__ out)
{
    int t = blockIdx.x;
    const float* xr = x + (size_t)t * D;
    float s = 0.f, s2 = 0.f;
    for (int i = threadIdx.x; i < D; i += 256) {
        float v = xr[i];
        s += v; s2 += v * v;
    }
    float tot = blockReduceSum(s);
    float tot2 = blockReduceSum(s2);
    float mean = tot * (1.f / D);
    float var = tot2 * (1.f / D) - mean * mean;
    float rstd = rsqrtf(var + LN_EPS);
    __half* orow = out + (size_t)t * D;
    for (int i = threadIdx.x; i < D; i += 256) {
        orow[i] = __float2half((xr[i] - mean) * rstd * g[i] + b[i]);
    }
}

// ---------------- FP16 GEMM NT, cp.async 3-stage, ldmatrix fragments ----------------
#define HT_PITCH 40
#define HT_STAGE (128 * HT_PITCH)
template<bool GELU, bool HASBIAS, bool HASRES, bool HALFOUT>
__global__ __launch_bounds__(256) void k_hgemm_nt(
    const __half* __restrict__ A, int lda,
    const __half* __restrict__ B, int ldb,
    void* __restrict__ Cv, int ldc,
    int K,
    const float* __restrict__ bias,
    const float* __restrict__ res, int ldres)
{
    int m0 = blockIdx.y * 128, n0 = blockIdx.x * 128;
    A += (size_t)m0 * lda;
    B += (size_t)n0 * ldb;

    extern __shared__ __half smh[];
    __half* Abuf = smh;
    __half* Bbuf = smh + 3 * HT_STAGE;

    int tid = threadIdx.x, lane = tid & 31, warp = tid >> 5;
    int wm = (warp & 1) * 64, wn = (warp >> 1) * 32;
    int lr = tid >> 1, lc = (tid & 1) * 8;

    // ldmatrix addressing: lane -> (row within m16/n16 tile, k half-select)
    int lrow16 = lane & 15;           // row within 16-row tile
    int lksel  = (lane >> 4) * 8;     // 0 or 8 (k halves)

    float acc[4][4][4] = {};

    auto load = [&](int st, int k0) {
        __half* As_ = Abuf + st * HT_STAGE;
        __half* Bs_ = Bbuf + st * HT_STAGE;
        cp16(As_ + lr * HT_PITCH + lc,      A + (size_t)lr * lda + k0 + lc);
        cp16(As_ + lr * HT_PITCH + lc + 16, A + (size_t)lr * lda + k0 + lc + 16);
        cp16(Bs_ + lr * HT_PITCH + lc,      B + (size_t)lr * ldb + k0 + lc);
        cp16(Bs_ + lr * HT_PITCH + lc + 16, B + (size_t)lr * ldb + k0 + lc + 16);
    };

    int nk = K / 32;
    load(0, 0); cp_commit();
    load(1, 32); cp_commit();

    for (int i = 0; i < nk; i++) {
        if (i + 1 < nk) cp_wait<1>(); else cp_wait<0>();
        __syncthreads();
        if (i + 2 < nk) { load((i + 2) % 3, (i + 2) * 32); cp_commit(); }

        const __half* As_ = Abuf + (i % 3) * HT_STAGE;
        const __half* Bs_ = Bbuf + (i % 3) * HT_STAGE;
        #pragma unroll
        for (int ks = 0; ks < 2; ks++) {
            int kh = ks * 16 + lksel;
            uint32_t af[4][4], bf[4][2];
            #pragma unroll
            for (int mf = 0; mf < 4; mf++) {
                ldsm_x4(af[mf][0], af[mf][1], af[mf][2], af[mf][3],
                        As_ + (wm + mf * 16 + lrow16) * HT_PITCH + kh);
            }
            #pragma unroll
            for (int nfp = 0; nfp < 2; nfp++) {
                ldsm_x4(bf[2 * nfp][0], bf[2 * nfp + 1][0],
                        bf[2 * nfp][1], bf[2 * nfp + 1][1],
                        Bs_ + (wn + nfp * 16 + lrow16) * HT_PITCH + kh);
            }
            #pragma unroll
            for (int mf = 0; mf < 4; mf++)
                #pragma unroll
                for (int nf = 0; nf < 4; nf++)
                    mma_f16(acc[mf][nf], af[mf], bf[nf]);
        }
        __syncthreads();
    }

    #pragma unroll
    for (int mf = 0; mf < 4; mf++) {
        int row = m0 + wm + mf * 16 + (lane >> 2);
        #pragma unroll
        for (int nf = 0; nf < 4; nf++) {
            int col = n0 + wn + nf * 8 + 2 * (lane & 3);
            #pragma unroll
            for (int half_ = 0; half_ < 2; half_++) {
                int r = row + half_ * 8;
                float v0 = acc[mf][nf][half_ * 2 + 0];
                float v1 = acc[mf][nf][half_ * 2 + 1];
                if (HASBIAS) { v0 += bias[col]; v1 += bias[col + 1]; }
                if (GELU) {
                    v0 = 0.5f * v0 * (1.f + erff(v0 * 0.70710678118654752f));
                    v1 = 0.5f * v1 * (1.f + erff(v1 * 0.70710678118654752f));
                }
                if (HASRES) {
                    v0 += res[(size_t)r * ldres + col];
                    v1 += res[(size_t)r * ldres + col + 1];
                }
                if (HALFOUT) {
                    *(__half2*)((__half*)Cv + (size_t)r * ldc + col) = __floats2half2_rn(v0, v1);
                } else {
                    float2 o = {v0, v1};
                    *(float2*)((float*)Cv + (size_t)r * ldc + col) = o;
                }
            }
        }
    }
}

// ---------------- fused dual-softmax flash attention (fp16 MMA) + causal sigmoid-sum ----------------
__global__ __launch_bounds__(256) void k_flash(
    const __half* __restrict__ qkv, const float* __restrict__ logm,
    __half* __restrict__ cat)
{
    extern __shared__ char smraw[];
    __half* sQh = (__half*)smraw;
    __half* sKh = (__half*)(smraw + 18432);
    __half* sVn = (__half*)(smraw + 36864);
    __half* sVt = (__half*)(smraw + 55296);
    __half* sP  = (__half*)(smraw + 73728);
    float*  sM  = (float*)(smraw + 110592);

    int bid = blockIdx.x;
    int qi = 15 - (bid >> 4);
    int h  = bid & 15;
    int q0 = qi * 128;
    int nkb = 2 * (qi + 1);

    int tid = threadIdx.x, lane = tid & 31, warp = tid >> 5;
    int p_ = lane >> 2, q_ = lane & 3;
    int wrow0 = warp * 16;

    #pragma unroll
    for (int i = 0; i < 4; i++) {
        int idx = tid + i * 256;
        int row = idx >> 3, ch = (idx & 7) * 8;
        cp16(sQh + row * 72 + ch, qkv + (size_t)(q0 + row) * D3 + h * 64 + ch);
    }
    #pragma unroll
    for (int i = 0; i < 2; i++) {
        int idx = tid + i * 256;
        int row = idx >> 3, ch = (idx & 7) * 8;
        cp16(sKh + row * 72 + ch, qkv + (size_t)row * D3 + D + h * 64 + ch);
        cp16(sVn + row * 72 + ch, qkv + (size_t)row * D3 + 2 * D + h * 64 + ch);
    }
    #pragma unroll
    for (int i = 0; i < 8; i++) {
        int idx = tid + i * 256;
        int row = idx >> 4, c4 = (idx & 15) * 4;
        cp16(sM + row * 68 + c4, logm + ((size_t)h * T + q0 + row) * T + c4);
    }
    cp_commit();

    float O1[8][4] = {}, O2[8][4] = {};
    float m1[2] = {-1e30f, -1e30f}, l1[2] = {0.f, 0.f};
    float m2[2] = {-1e30f, -1e30f}, l2[2] = {0.f, 0.f};
    float ssum = 0.f;

    int r0 = wrow0 + p_;
    int t0 = q0 + r0, t1 = t0 + 8;
    __half* sP1 = sP + warp * 1152;
    __half* sP2 = sP + 9216 + warp * 1152;

    int vdh = tid & 63;
    int vtb = (tid >> 6) * 16;

    for (int j = 0; j < nkb; j++) {
        int st = j & 1;
        int kb0 = j * 64;
        cp_wait<0>();
        __syncthreads();
        if (j + 1 < nkb) {
            int st2 = st ^ 1, kb2 = kb0 + 64;
            __half* dK = sKh + st2 * 4608;
            __half* dV = sVn + st2 * 4608;
            float*  dM = sM  + st2 * 8704;
            #pragma unroll
            for (int i = 0; i < 2; i++) {
                int idx = tid + i * 256;
                int row = idx >> 3, ch = (idx & 7) * 8;
                cp16(dK + row * 72 + ch, qkv + (size_t)(kb2 + row) * D3 + D + h * 64 + ch);
                cp16(dV + row * 72 + ch, qkv + (size_t)(kb2 + row) * D3 + 2 * D + h * 64 + ch);
            }
            #pragma unroll
            for (int i = 0; i < 8; i++) {
                int idx = tid + i * 256;
                int row = idx >> 4, c4 = (idx & 15) * 4;
                cp16(dM + row * 68 + c4, logm + ((size_t)h * T + q0 + row) * T + kb2 + c4);
            }
            cp_commit();
        }

        const __half* sKs = sKh + st * 4608;
        const __half* sVns = sVn + st * 4608;
        __half* sVts = sVt + st * 4608;
        const float* sMs = sM + st * 8704;

        #pragma unroll
        for (int t2 = 0; t2 < 16; t2 += 2) {
            int tok = vtb + t2;
            __half a = sVns[tok * 72 + vdh];
            __half b = sVns[(tok + 1) * 72 + vdh];
            *(__half2*)(sVts + vdh * 72 + tok) = __halves2half2(a, b);
        }
        __syncthreads();

        float sg[8][4];
        #pragma unroll
        for (int nf = 0; nf < 8; nf++) {
            int c0 = nf * 8 + 2 * q_;
            float2 a = *(const float2*)(sMs + r0 * 68 + c0);
            float2 b = *(const float2*)(sMs + (r0 + 8) * 68 + c0);
            sg[nf][0] = sigf(a.x); sg[nf][1] = sigf(a.y);
            sg[nf][2] = sigf(b.x); sg[nf][3] = sigf(b.y);
            ssum += sg[nf][0] + sg[nf][1] + sg[nf][2] + sg[nf][3];
        }

        if (kb0 > q0 + wrow0 + 15) continue;

        float sc[8][4] = {};
        #pragma unroll
        for (int kc = 0; kc < 4; kc++) {
            int kh = kc * 16 + 2 * q_;
            uint32_t af[4];
            af[0] = *(const uint32_t*)(sQh + r0 * 72 + kh);
            af[1] = *(const uint32_t*)(sQh + (r0 + 8) * 72 + kh);
            af[2] = *(const uint32_t*)(sQh + r0 * 72 + kh + 8);
            af[3] = *(const uint32_t*)(sQh + (r0 + 8) * 72 + kh + 8);
            #pragma unroll
            for (int nf = 0; nf < 8; nf++) {
                uint32_t bf[2];
                bf[0] = *(const uint32_t*)(sKs + (nf * 8 + p_) * 72 + kh);
                bf[1] = *(const uint32_t*)(sKs + (nf * 8 + p_) * 72 + kh + 8);
                mma_f16(sc[nf], af, bf);
            }
        }
        #pragma unroll
        for (int nf = 0; nf < 8; nf++) {
            sc[nf][0] *= 0.125f; sc[nf][1] *= 0.125f;
            sc[nf][2] *= 0.125f; sc[nf][3] *= 0.125f;
        }

        #pragma unroll
        for (int br = 0; br < 2; br++) {
            float* mB = br ? m2 : m1;
            float* lB = br ? l2 : l1;
            float (*OB)[4] = br ? O2 : O1;
            __half* sPw = br ? sP2 : sP1;

            float v[8][4];
            float rmx0 = -1e30f, rmx1 = -1e30f;
            #pragma unroll
            for (int nf = 0; nf < 8; nf++) {
                int c0 = kb0 + nf * 8 + 2 * q_;
                float w0 = br ? sc[nf][0] * sg[nf][0] : sc[nf][0];
                float w1 = br ? sc[nf][1] * sg[nf][1] : sc[nf][1];
                float w2 = br ? sc[nf][2] * sg[nf][2] : sc[nf][2];
                float w3 = br ? sc[nf][3] * sg[nf][3] : sc[nf][3];
                v[nf][0] = (c0     <= t0) ? w0 : -1e30f;
                v[nf][1] = (c0 + 1 <= t0) ? w1 : -1e30f;
                v[nf][2] = (c0     <= t1) ? w2 : -1e30f;
                v[nf][3] = (c0 + 1 <= t1) ? w3 : -1e30f;
                rmx0 = fmaxf(rmx0, fmaxf(v[nf][0], v[nf][1]));
                rmx1 = fmaxf(rmx1, fmaxf(v[nf][2], v[nf][3]));
            }
            rmx0 = fmaxf(rmx0, __shfl_xor_sync(0xffffffff, rmx0, 1));
            rmx0 = fmaxf(rmx0, __shfl_xor_sync(0xffffffff, rmx0, 2));
            rmx1 = fmaxf(rmx1, __shfl_xor_sync(0xffffffff, rmx1, 1));
            rmx1 = fmaxf(rmx1, __shfl_xor_sync(0xffffffff, rmx1, 2));

            float mn0 = fmaxf(mB[0], rmx0), mn1 = fmaxf(mB[1], rmx1);
            float al0 = __expf(mB[0] - mn0), al1 = __expf(mB[1] - mn1);
            float rs0 = 0.f, rs1 = 0.f;
            #pragma unroll
            for (int nf = 0; nf < 8; nf++) {
                v[nf][0] = __expf(v[nf][0] - mn0);
                v[nf][1] = __expf(v[nf][1] - mn0);
                v[nf][2] = __expf(v[nf][2] - mn1);
                v[nf][3] = __expf(v[nf][3] - mn1);
                rs0 += v[nf][0] + v[nf][1];
                rs1 += v[nf][2] + v[nf][3];
            }
            rs0 += __shfl_xor_sync(0xffffffff, rs0, 1);
            rs0 += __shfl_xor_sync(0xffffffff, rs0, 2);
            rs1 += __shfl_xor_sync(0xffffffff, rs1, 1);
            rs1 += __shfl_xor_sync(0xffffffff, rs1, 2);
            lB[0] = lB[0] * al0 + rs0; lB[1] = lB[1] * al1 + rs1;
            mB[0] = mn0; mB[1] = mn1;

            #pragma unroll
            for (int nf = 0; nf < 8; nf++) {
                OB[nf][0] *= al0; OB[nf][1] *= al0;
                OB[nf][2] *= al1; OB[nf][3] *= al1;
                *(__half2*)(sPw + p_ * 72 + nf * 8 + 2 * q_)       = __floats2half2_rn(v[nf][0], v[nf][1]);
                *(__half2*)(sPw + (p_ + 8) * 72 + nf * 8 + 2 * q_) = __floats2half2_rn(v[nf][2], v[nf][3]);
            }
        }
        __syncwarp();

        #pragma unroll
        for (int kc = 0; kc < 4; kc++) {
            int kh = kc * 16 + 2 * q_;
            uint32_t a1f[4], a2f[4];
            a1f[0] = *(const uint32_t*)(sP1 + p_ * 72 + kh);
            a1f[1] = *(const uint32_t*)(sP1 + (p_ + 8) * 72 + kh);
            a1f[2] = *(const uint32_t*)(sP1 + p_ * 72 + kh + 8);
            a1f[3] = *(const uint32_t*)(sP1 + (p_ + 8) * 72 + kh + 8);
            a2f[0] = *(const uint32_t*)(sP2 + p_ * 72 + kh);
            a2f[1] = *(const uint32_t*)(sP2 + (p_ + 8) * 72 + kh);
            a2f[2] = *(const uint32_t*)(sP2 + p_ * 72 + kh + 8);
            a2f[3] = *(const uint32_t*)(sP2 + (p_ + 8) * 72 + kh + 8);
            #pragma unroll
            for (int nf = 0; nf < 8; nf++) {
                uint32_t bf[2];
                bf[0] = *(const uint32_t*)(sVts + (nf * 8 + p_) * 72 + kh);
                bf[1] = *(const uint32_t*)(sVts + (nf * 8 + p_) * 72 + kh + 8);
                mma_f16(O1[nf], a1f, bf);
                mma_f16(O2[nf], a2f, bf);
            }
        }
    }

    float rl10 = 1.f / l1[0], rl11 = 1.f / l1[1];
    float rl20 = 1.f / l2[0], rl21 = 1.f / l2[1];
    int row = q0 + wrow0 + p_;
    #pragma unroll
    for (int nf = 0; nf < 8; nf++) {
        int col = h * 64 + nf * 8 + 2 * q_;
        *(__half2*)(cat + (size_t)row * D2 + col)           = __floats2half2_rn(O1[nf][0] * rl10, O1[nf][1] * rl10);
        *(__half2*)(cat + (size_t)(row + 8) * D2 + col)     = __floats2half2_rn(O1[nf][2] * rl11, O1[nf][3] * rl11);
        *(__half2*)(cat + (size_t)row * D2 + D + col)       = __floats2half2_rn(O2[nf][0] * rl20, O2[nf][1] * rl20);
        *(__half2*)(cat + (size_t)(row + 8) * D2 + D + col) = __floats2half2_rn(O2[nf][2] * rl21, O2[nf][3] * rl21);
    }

    float tot = blockReduceSum(ssum);
    if (tid == 0) atomicAdd(&g_sigacc, (double)tot);
}

// ---------------- sigmoid sum over strictly-upper 128x128 tiles ----------------
__global__ __launch_bounds__(256) void k_sig_upper(const float* __restrict__ lm)
{
    int i = blockIdx.x, qi = 0, cnt = 15;
    while (i >= cnt) { i -= cnt; qi++; cnt--; }
    int cb = qi + 1 + i;
    int h = blockIdx.y;
    const float* base = lm + ((size_t)h * T + qi * 128) * T + cb * 128;

    float s = 0.f;
    int tr = threadIdx.x >> 5;
    int tc = (threadIdx.x & 31) * 4;
    #pragma unroll
    for (int rr = 0; rr < 16; rr++) {
        int row = tr * 16 + rr;
        float4 v = *(const float4*)(base + (size_t)row * T + tc);
        s += sigf(v.x) + sigf(v.y) + sigf(v.z) + sigf(v.w);
    }
    float tot = blockReduceSum(s);
    if (threadIdx.x == 0) atomicAdd(&g_sigacc, (double)tot);
}

__global__ void k_zero_acc() { g_sigacc = 0.0; }

__global__ void k_write_sp(float* out, int out_size)
{
    const long long TD = (long long)T * D;
    if (out_size > TD) {
        double mean = g_sigacc / ((double)H * (double)T * (double)T);
        out[TD] = (float)(SPARSITY_LAMBDA * mean);
    }
}

// ---------------- launch ----------------
#define HT_SMEM (6 * HT_STAGE * sizeof(__half))  // 61440
#define FL_SMEM 180224

extern "C" void kernel_launch(void* const* d_in, const int* in_sizes, int n_in,
                              void* d_out, int out_size)
{
    const float* x      = (const float*)d_in[0];
    const float* W_qkv  = (const float*)d_in[2];
    const float* W_out  = (const float*)d_in[3];
    const float* logm   = (const float*)d_in[4];
    const float* W_gate = (const float*)d_in[5];
    const float* b_gate = (const float*)d_in[6];
    const float* g1     = (const float*)d_in[7];
    const float* b1     = (const float*)d_in[8];
    const float* g2     = (const float*)d_in[9];
    const float* b2     = (const float*)d_in[10];
    const float* W_ff1  = (const float*)d_in[11];
    const float* b_ff1  = (const float*)d_in[12];
    const float* W_ff2  = (const float*)d_in[13];
    const float* b_ff2  = (const float*)d_in[14];
    float* out = (float*)d_out;

    __half *xnh, *qkvh, *cath, *tmph, *hnh, *ffh;
    __half *wqkvh, *wgateh, *wouth, *wff1h, *wff2h;
    float *hbuf;
    cudaGetSymbolAddress((void**)&xnh,   g_xnh);
    cudaGetSymbolAddress((void**)&qkvh,  g_qkvh);
    cudaGetSymbolAddress((void**)&cath,  g_cath);
    cudaGetSymbolAddress((void**)&tmph,  g_tmph);
    cudaGetSymbolAddress((void**)&hbuf,  g_h);
    cudaGetSymbolAddress((void**)&hnh,   g_hnh);
    cudaGetSymbolAddress((void**)&ffh,   g_ffh);
    cudaGetSymbolAddress((void**)&wqkvh, g_wqkvh);
    cudaGetSymbolAddress((void**)&wgateh, g_wgateh);
    cudaGetSymbolAddress((void**)&wouth, g_wouth);
    cudaGetSymbolAddress((void**)&wff1h, g_wff1h);
    cudaGetSymbolAddress((void**)&wff2h, g_wff2h);

    cudaFuncSetAttribute(k_hgemm_nt<false, false, false, true >, cudaFuncAttributeMaxDynamicSharedMemorySize, HT_SMEM);
    cudaFuncSetAttribute(k_hgemm_nt<false, true,  false, true >, cudaFuncAttributeMaxDynamicSharedMemorySize, HT_SMEM);
    cudaFuncSetAttribute(k_hgemm_nt<false, false, true,  false>, cudaFuncAttributeMaxDynamicSharedMemorySize, HT_SMEM);
    cudaFuncSetAttribute(k_hgemm_nt<true,  true,  false, true >, cudaFuncAttributeMaxDynamicSharedMemorySize, HT_SMEM);
    cudaFuncSetAttribute(k_hgemm_nt<false, true,  true,  false>, cudaFuncAttributeMaxDynamicSharedMemorySize, HT_SMEM);
    cudaFuncSetAttribute(k_flash, cudaFuncAttributeMaxDynamicSharedMemorySize, FL_SMEM);

    k_zero_acc<<<1, 1>>>();

    // all weight conversions in one launch
    k_f2h_all<<<1184, 256>>>(W_qkv, W_gate, W_out, W_ff1, W_ff2,
                             wqkvh, wgateh, wouth, wff1h, wff2h);

    // ln1 -> half
    k_layernorm_h<<<T, 256>>>(x, g1, b1, xnh);

    // qkv = xn @ W_qkv^T (half out)
    k_hgemm_nt<false, false, false, true><<<dim3(D3 / 128, T / 128), 256, HT_SMEM>>>(
        xnh, D, wqkvh, D, qkvh, D3, D, nullptr, nullptr, 0);

    // strictly-upper sigmoid sum (causal part accumulated inside flash)
    k_sig_upper<<<dim3(120, H), 256>>>(logm);

    // fused dual-softmax attention -> cat (half) + causal sigmoid sum
    k_flash<<<256, 256, FL_SMEM>>>(qkvh, logm, cath);

    // tmp = cat @ W_gate^T + b_gate  (half out)
    k_hgemm_nt<false, true, false, true><<<dim3(D / 128, T / 128), 256, HT_SMEM>>>(
        cath, D2, wgateh, D2, tmph, D, D2, b_gate, nullptr, 0);

    // h = x + tmp @ W_out^T  (fp32 out)
    k_hgemm_nt<false, false, true, false><<<dim3(D / 128, T / 128), 256, HT_SMEM>>>(
        tmph, D, wouth, D, hbuf, D, D, nullptr, x, D);

    // ln2 -> half
    k_layernorm_h<<<T, 256>>>(hbuf, g2, b2, hnh);

    // ff = gelu(hn @ W_ff1^T + b_ff1)  (half out)
    k_hgemm_nt<true, true, false, true><<<dim3(DFF / 128, T / 128), 256, HT_SMEM>>>(
        hnh, D, wff1h, D, ffh, DFF, D, b_ff1, nullptr, 0);

    // out = h + ff @ W_ff2^T + b_ff2  (fp32 out)
    k_hgemm_nt<false, true, true, false><<<dim3(D / 128, T / 128), 256, HT_SMEM>>>(
        ffh, DFF, wff2h, DFF, out, D, DFF, b_ff2, hbuf, D);

    k_write_sp<<<1, 1>>>(out, out_size);
}

// round 14
// speedup vs baseline: 1.1034x; 1.1034x over previous
#include <cuda_runtime.h>
#include <cuda_fp16.h>
#include <math_constants.h>
#include <cstdint>

#define T 2048
#define D 1024
#define H 16
#define DH 64
#define D3 3072
#define D2 2048
#define DFF 4096
#define LN_EPS 1e-5f
#define SPARSITY_LAMBDA 0.0005f

// ---------------- scratch ----------------
__device__ __half g_xnh[(size_t)T * D];
__device__ __half g_qkvh[(size_t)T * D3];
__device__ __half g_cath[(size_t)T * D2];
__device__ __half g_tmph[(size_t)T * D];
__device__ float  g_h[(size_t)T * D];
__device__ __half g_hnh[(size_t)T * D];
__device__ __half g_ffh[(size_t)T * DFF];
__device__ __half g_wqkvh[(size_t)D3 * D];
__device__ __half g_wgateh[(size_t)D * D2];
__device__ __half g_wouth[(size_t)D * D];
__device__ __half g_wff1h[(size_t)DFF * D];
__device__ __half g_wff2h[(size_t)D * DFF];
__device__ double g_sigacc;

// ---------------- helpers ----------------
__device__ __forceinline__ void mma_f16(float (&d)[4], const uint32_t (&a)[4], const uint32_t (&b)[2]) {
    asm volatile(
        "mma.sync.aligned.m16n8k16.row.col.f32.f16.f16.f32 "
        "{%0,%1,%2,%3}, {%4,%5,%6,%7}, {%8,%9}, {%0,%1,%2,%3};\n"
        : "+f"(d[0]), "+f"(d[1]), "+f"(d[2]), "+f"(d[3])
        : "r"(a[0]), "r"(a[1]), "r"(a[2]), "r"(a[3]), "r"(b[0]), "r"(b[1]));
}

__device__ __forceinline__ void cp16(void* sdst, const void* gsrc) {
    uint32_t s = (uint32_t)__cvta_generic_to_shared(sdst);
    asm volatile("cp.async.cg.shared.global [%0], [%1], 16;" :: "r"(s), "l"(gsrc));
}
__device__ __forceinline__ void cp_commit() { asm volatile("cp.async.commit_group;"); }
template<int N> __device__ __forceinline__ void cp_wait() {
    asm volatile("cp.async.wait_group %0;" :: "n"(N));
}

__device__ __forceinline__ float sigf(float x) { return 1.f / (1.f + __expf(-x)); }

__device__ __forceinline__ float blockReduceSum(float v) {
    __shared__ float red[32];
    int lane = threadIdx.x & 31, wid = threadIdx.x >> 5;
    #pragma unroll
    for (int o = 16; o > 0; o >>= 1) v += __shfl_xor_sync(0xffffffff, v, o);
    __syncthreads();
    if (lane == 0) red[wid] = v;
    __syncthreads();
    int nw = (blockDim.x + 31) >> 5;
    float r = (threadIdx.x < nw) ? red[threadIdx.x] : 0.f;
    if (wid == 0) {
        #pragma unroll
        for (int o = 16; o > 0; o >>= 1) r += __shfl_xor_sync(0xffffffff, r, o);
        if (lane == 0) red[0] = r;
    }
    __syncthreads();
    return red[0];
}

// ---------------- merged fp32 -> fp16 conversion for all 5 weights ----------------
#define N4_QKV  786432
#define N4_GATE 524288
#define N4_OUT  262144
#define N4_FF1  1048576
#define N4_FF2  1048576
#define N4_TOT  (N4_QKV + N4_GATE + N4_OUT + N4_FF1 + N4_FF2)

__global__ __launch_bounds__(256) void k_f2h_all(
    const float* __restrict__ wqkv, const float* __restrict__ wgate,
    const float* __restrict__ wout, const float* __restrict__ wff1,
    const float* __restrict__ wff2,
    __half* __restrict__ hqkv, __half* __restrict__ hgate,
    __half* __restrict__ hout, __half* __restrict__ hff1,
    __half* __restrict__ hff2)
{
    for (int i = blockIdx.x * 256 + threadIdx.x; i < N4_TOT; i += gridDim.x * 256) {
        const float* src; __half* dst; int off;
        if (i < N4_QKV)                         { src = wqkv;  dst = hqkv;  off = i; }
        else if (i < N4_QKV + N4_GATE)          { src = wgate; dst = hgate; off = i - N4_QKV; }
        else if (i < N4_QKV + N4_GATE + N4_OUT) { src = wout;  dst = hout;  off = i - N4_QKV - N4_GATE; }
        else if (i < N4_QKV + N4_GATE + N4_OUT + N4_FF1)
                                                { src = wff1;  dst = hff1;  off = i - N4_QKV - N4_GATE - N4_OUT; }
        else                                    { src = wff2;  dst = hff2;  off = i - N4_QKV - N4_GATE - N4_OUT - N4_FF1; }
        float4 v = *(const float4*)(src + (size_t)off * 4);
        __half2* o = (__half2*)(dst + (size_t)off * 4);
        o[0] = __floats2half2_rn(v.x, v.y);
        o[1] = __floats2half2_rn(v.z, v.w);
    }
}

// ---------------- layernorm (half output) ----------------
__global__ __launch_bounds__(256) void k_layernorm_h(
    const float* __restrict__ x, const float* __restrict__ g,
    const float* __restrict__ b, __half* __restrict__ out)
{
    int t = blockIdx.x;
    const float* xr = x + (size_t)t * D;
    float s = 0.f, s2 = 0.f;
    for (int i = threadIdx.x; i < D; i += 256) {
        float v = xr[i];
        s += v; s2 += v * v;
    }
    float tot = blockReduceSum(s);
    float tot2 = blockReduceSum(s2);
    float mean = tot * (1.f / D);
    float var = tot2 * (1.f / D) - mean * mean;
    float rstd = rsqrtf(var + LN_EPS);
    __half* orow = out + (size_t)t * D;
    for (int i = threadIdx.x; i < D; i += 256) {
        orow[i] = __float2half((xr[i] - mean) * rstd * g[i] + b[i]);
    }
}

// ---------------- FP16 GEMM NT, 512 threads, 32x32 warp tiles, 3-stage cp.async ----------------
#define HT_PITCH 40
#define HT_STAGE (128 * HT_PITCH)
#define HT_SMEM (6 * HT_STAGE * sizeof(__half))  // 61440
template<bool GELU, bool HASBIAS, bool HASRES, bool HALFOUT>
__global__ __launch_bounds__(512, 2) void k_hgemm_nt(
    const __half* __restrict__ A, int lda,
    const __half* __restrict__ B, int ldb,
    void* __restrict__ Cv, int ldc,
    int K,
    const float* __restrict__ bias,
    const float* __restrict__ res, int ldres)
{
    int m0 = blockIdx.y * 128, n0 = blockIdx.x * 128;
    A += (size_t)m0 * lda;
    B += (size_t)n0 * ldb;

    extern __shared__ __half smh[];
    __half* Abuf = smh;
    __half* Bbuf = smh + 3 * HT_STAGE;

    int tid = threadIdx.x, lane = tid & 31, warp = tid >> 5;
    int wm = (warp & 3) * 32, wn = (warp >> 2) * 32;
    int lr = tid >> 2, lc = (tid & 3) * 8;   // 512 thr: row 0..127, col 0/8/16/24

    float acc[2][4][4] = {};

    auto load = [&](int st, int k0) {
        __half* As_ = Abuf + st * HT_STAGE;
        __half* Bs_ = Bbuf + st * HT_STAGE;
        cp16(As_ + lr * HT_PITCH + lc, A + (size_t)lr * lda + k0 + lc);
        cp16(Bs_ + lr * HT_PITCH + lc, B + (size_t)lr * ldb + k0 + lc);
    };

    int nk = K / 32;
    load(0, 0); cp_commit();
    load(1, 32); cp_commit();

    for (int i = 0; i < nk; i++) {
        if (i + 1 < nk) cp_wait<1>(); else cp_wait<0>();
        __syncthreads();
        if (i + 2 < nk) { load((i + 2) % 3, (i + 2) * 32); cp_commit(); }

        const __half* As_ = Abuf + (i % 3) * HT_STAGE;
        const __half* Bs_ = Bbuf + (i % 3) * HT_STAGE;
        #pragma unroll
        for (int ks = 0; ks < 2; ks++) {
            int kh = ks * 16 + (lane & 3) * 2;
            uint32_t af[2][4], bf[4][2];
            #pragma unroll
            for (int mf = 0; mf < 2; mf++) {
                int r = wm + mf * 16 + (lane >> 2);
                af[mf][0] = *(const uint32_t*)(As_ + r * HT_PITCH + kh);
                af[mf][1] = *(const uint32_t*)(As_ + (r + 8) * HT_PITCH + kh);
                af[mf][2] = *(const uint32_t*)(As_ + r * HT_PITCH + kh + 8);
                af[mf][3] = *(const uint32_t*)(As_ + (r + 8) * HT_PITCH + kh + 8);
            }
            #pragma unroll
            for (int nf = 0; nf < 4; nf++) {
                int n = wn + nf * 8 + (lane >> 2);
                bf[nf][0] = *(const uint32_t*)(Bs_ + n * HT_PITCH + kh);
                bf[nf][1] = *(const uint32_t*)(Bs_ + n * HT_PITCH + kh + 8);
            }
            #pragma unroll
            for (int mf = 0; mf < 2; mf++)
                #pragma unroll
                for (int nf = 0; nf < 4; nf++)
                    mma_f16(acc[mf][nf], af[mf], bf[nf]);
        }
        __syncthreads();
    }

    #pragma unroll
    for (int mf = 0; mf < 2; mf++) {
        int row = m0 + wm + mf * 16 + (lane >> 2);
        #pragma unroll
        for (int nf = 0; nf < 4; nf++) {
            int col = n0 + wn + nf * 8 + 2 * (lane & 3);
            #pragma unroll
            for (int half_ = 0; half_ < 2; half_++) {
                int r = row + half_ * 8;
                float v0 = acc[mf][nf][half_ * 2 + 0];
                float v1 = acc[mf][nf][half_ * 2 + 1];
                if (HASBIAS) { v0 += bias[col]; v1 += bias[col + 1]; }
                if (GELU) {
                    v0 = 0.5f * v0 * (1.f + erff(v0 * 0.70710678118654752f));
                    v1 = 0.5f * v1 * (1.f + erff(v1 * 0.70710678118654752f));
                }
                if (HASRES) {
                    v0 += res[(size_t)r * ldres + col];
                    v1 += res[(size_t)r * ldres + col + 1];
                }
                if (HALFOUT) {
                    *(__half2*)((__half*)Cv + (size_t)r * ldc + col) = __floats2half2_rn(v0, v1);
                } else {
                    float2 o = {v0, v1};
                    *(float2*)((float*)Cv + (size_t)r * ldc + col) = o;
                }
            }
        }
    }
}

// ---------------- fused dual-softmax flash attention (fp16 MMA) + causal sigmoid-sum ----------------
__global__ __launch_bounds__(256) void k_flash(
    const __half* __restrict__ qkv, const float* __restrict__ logm,
    __half* __restrict__ cat)
{
    extern __shared__ char smraw[];
    __half* sQh = (__half*)smraw;
    __half* sKh = (__half*)(smraw + 18432);
    __half* sVn = (__half*)(smraw + 36864);
    __half* sVt = (__half*)(smraw + 55296);
    __half* sP  = (__half*)(smraw + 73728);
    float*  sM  = (float*)(smraw + 110592);

    int bid = blockIdx.x;
    int qi = 15 - (bid >> 4);
    int h  = bid & 15;
    int q0 = qi * 128;
    int nkb = 2 * (qi + 1);

    int tid = threadIdx.x, lane = tid & 31, warp = tid >> 5;
    int p_ = lane >> 2, q_ = lane & 3;
    int wrow0 = warp * 16;

    #pragma unroll
    for (int i = 0; i < 4; i++) {
        int idx = tid + i * 256;
        int row = idx >> 3, ch = (idx & 7) * 8;
        cp16(sQh + row * 72 + ch, qkv + (size_t)(q0 + row) * D3 + h * 64 + ch);
    }
    #pragma unroll
    for (int i = 0; i < 2; i++) {
        int idx = tid + i * 256;
        int row = idx >> 3, ch = (idx & 7) * 8;
        cp16(sKh + row * 72 + ch, qkv + (size_t)row * D3 + D + h * 64 + ch);
        cp16(sVn + row * 72 + ch, qkv + (size_t)row * D3 + 2 * D + h * 64 + ch);
    }
    #pragma unroll
    for (int i = 0; i < 8; i++) {
        int idx = tid + i * 256;
        int row = idx >> 4, c4 = (idx & 15) * 4;
        cp16(sM + row * 68 + c4, logm + ((size_t)h * T + q0 + row) * T + c4);
    }
    cp_commit();

    float O1[8][4] = {}, O2[8][4] = {};
    float m1[2] = {-1e30f, -1e30f}, l1[2] = {0.f, 0.f};
    float m2[2] = {-1e30f, -1e30f}, l2[2] = {0.f, 0.f};
    float ssum = 0.f;

    int r0 = wrow0 + p_;
    int t0 = q0 + r0, t1 = t0 + 8;
    __half* sP1 = sP + warp * 1152;
    __half* sP2 = sP + 9216 + warp * 1152;

    int vdh = tid & 63;
    int vtb = (tid >> 6) * 16;

    for (int j = 0; j < nkb; j++) {
        int st = j & 1;
        int kb0 = j * 64;
        cp_wait<0>();
        __syncthreads();
        if (j + 1 < nkb) {
            int st2 = st ^ 1, kb2 = kb0 + 64;
            __half* dK = sKh + st2 * 4608;
            __half* dV = sVn + st2 * 4608;
            float*  dM = sM  + st2 * 8704;
            #pragma unroll
            for (int i = 0; i < 2; i++) {
                int idx = tid + i * 256;
                int row = idx >> 3, ch = (idx & 7) * 8;
                cp16(dK + row * 72 + ch, qkv + (size_t)(kb2 + row) * D3 + D + h * 64 + ch);
                cp16(dV + row * 72 + ch, qkv + (size_t)(kb2 + row) * D3 + 2 * D + h * 64 + ch);
            }
            #pragma unroll
            for (int i = 0; i < 8; i++) {
                int idx = tid + i * 256;
                int row = idx >> 4, c4 = (idx & 15) * 4;
                cp16(dM + row * 68 + c4, logm + ((size_t)h * T + q0 + row) * T + kb2 + c4);
            }
            cp_commit();
        }

        const __half* sKs = sKh + st * 4608;
        const __half* sVns = sVn + st * 4608;
        __half* sVts = sVt + st * 4608;
        const float* sMs = sM + st * 8704;

        #pragma unroll
        for (int t2 = 0; t2 < 16; t2 += 2) {
            int tok = vtb + t2;
            __half a = sVns[tok * 72 + vdh];
            __half b = sVns[(tok + 1) * 72 + vdh];
            *(__half2*)(sVts + vdh * 72 + tok) = __halves2half2(a, b);
        }
        __syncthreads();

        float sg[8][4];
        #pragma unroll
        for (int nf = 0; nf < 8; nf++) {
            int c0 = nf * 8 + 2 * q_;
            float2 a = *(const float2*)(sMs + r0 * 68 + c0);
            float2 b = *(const float2*)(sMs + (r0 + 8) * 68 + c0);
            sg[nf][0] = sigf(a.x); sg[nf][1] = sigf(a.y);
            sg[nf][2] = sigf(b.x); sg[nf][3] = sigf(b.y);
            ssum += sg[nf][0] + sg[nf][1] + sg[nf][2] + sg[nf][3];
        }

        if (kb0 > q0 + wrow0 + 15) continue;

        float sc[8][4] = {};
        #pragma unroll
        for (int kc = 0; kc < 4; kc++) {
            int kh = kc * 16 + 2 * q_;
            uint32_t af[4];
            af[0] = *(const uint32_t*)(sQh + r0 * 72 + kh);
            af[1] = *(const uint32_t*)(sQh + (r0 + 8) * 72 + kh);
            af[2] = *(const uint32_t*)(sQh + r0 * 72 + kh + 8);
            af[3] = *(const uint32_t*)(sQh + (r0 + 8) * 72 + kh + 8);
            #pragma unroll
            for (int nf = 0; nf < 8; nf++) {
                uint32_t bf[2];
                bf[0] = *(const uint32_t*)(sKs + (nf * 8 + p_) * 72 + kh);
                bf[1] = *(const uint32_t*)(sKs + (nf * 8 + p_) * 72 + kh + 8);
                mma_f16(sc[nf], af, bf);
            }
        }
        #pragma unroll
        for (int nf = 0; nf < 8; nf++) {
            sc[nf][0] *= 0.125f; sc[nf][1] *= 0.125f;
            sc[nf][2] *= 0.125f; sc[nf][3] *= 0.125f;
        }

        #pragma unroll
        for (int br = 0; br < 2; br++) {
            float* mB = br ? m2 : m1;
            float* lB = br ? l2 : l1;
            float (*OB)[4] = br ? O2 : O1;
            __half* sPw = br ? sP2 : sP1;

            float v[8][4];
            float rmx0 = -1e30f, rmx1 = -1e30f;
            #pragma unroll
            for (int nf = 0; nf < 8; nf++) {
                int c0 = kb0 + nf * 8 + 2 * q_;
                float w0 = br ? sc[nf][0] * sg[nf][0] : sc[nf][0];
                float w1 = br ? sc[nf][1] * sg[nf][1] : sc[nf][1];
                float w2 = br ? sc[nf][2] * sg[nf][2] : sc[nf][2];
                float w3 = br ? sc[nf][3] * sg[nf][3] : sc[nf][3];
                v[nf][0] = (c0     <= t0) ? w0 : -1e30f;
                v[nf][1] = (c0 + 1 <= t0) ? w1 : -1e30f;
                v[nf][2] = (c0     <= t1) ? w2 : -1e30f;
                v[nf][3] = (c0 + 1 <= t1) ? w3 : -1e30f;
                rmx0 = fmaxf(rmx0, fmaxf(v[nf][0], v[nf][1]));
                rmx1 = fmaxf(rmx1, fmaxf(v[nf][2], v[nf][3]));
            }
            rmx0 = fmaxf(rmx0, __shfl_xor_sync(0xffffffff, rmx0, 1));
            rmx0 = fmaxf(rmx0, __shfl_xor_sync(0xffffffff, rmx0, 2));
            rmx1 = fmaxf(rmx1, __shfl_xor_sync(0xffffffff, rmx1, 1));
            rmx1 = fmaxf(rmx1, __shfl_xor_sync(0xffffffff, rmx1, 2));

            float mn0 = fmaxf(mB[0], rmx0), mn1 = fmaxf(mB[1], rmx1);
            float al0 = __expf(mB[0] - mn0), al1 = __expf(mB[1] - mn1);
            float rs0 = 0.f, rs1 = 0.f;
            #pragma unroll
            for (int nf = 0; nf < 8; nf++) {
                v[nf][0] = __expf(v[nf][0] - mn0);
                v[nf][1] = __expf(v[nf][1] - mn0);
                v[nf][2] = __expf(v[nf][2] - mn1);
                v[nf][3] = __expf(v[nf][3] - mn1);
                rs0 += v[nf][0] + v[nf][1];
                rs1 += v[nf][2] + v[nf][3];
            }
            rs0 += __shfl_xor_sync(0xffffffff, rs0, 1);
            rs0 += __shfl_xor_sync(0xffffffff, rs0, 2);
            rs1 += __shfl_xor_sync(0xffffffff, rs1, 1);
            rs1 += __shfl_xor_sync(0xffffffff, rs1, 2);
            lB[0] = lB[0] * al0 + rs0; lB[1] = lB[1] * al1 + rs1;
            mB[0] = mn0; mB[1] = mn1;

            #pragma unroll
            for (int nf = 0; nf < 8; nf++) {
                OB[nf][0] *= al0; OB[nf][1] *= al0;
                OB[nf][2] *= al1; OB[nf][3] *= al1;
                *(__half2*)(sPw + p_ * 72 + nf * 8 + 2 * q_)       = __floats2half2_rn(v[nf][0], v[nf][1]);
                *(__half2*)(sPw + (p_ + 8) * 72 + nf * 8 + 2 * q_) = __floats2half2_rn(v[nf][2], v[nf][3]);
            }
        }
        __syncwarp();

        #pragma unroll
        for (int kc = 0; kc < 4; kc++) {
            int kh = kc * 16 + 2 * q_;
            uint32_t a1f[4], a2f[4];
            a1f[0] = *(const uint32_t*)(sP1 + p_ * 72 + kh);
            a1f[1] = *(const uint32_t*)(sP1 + (p_ + 8) * 72 + kh);
            a1f[2] = *(const uint32_t*)(sP1 + p_ * 72 + kh + 8);
            a1f[3] = *(const uint32_t*)(sP1 + (p_ + 8) * 72 + kh + 8);
            a2f[0] = *(const uint32_t*)(sP2 + p_ * 72 + kh);
            a2f[1] = *(const uint32_t*)(sP2 + (p_ + 8) * 72 + kh);
            a2f[2] = *(const uint32_t*)(sP2 + p_ * 72 + kh + 8);
            a2f[3] = *(const uint32_t*)(sP2 + (p_ + 8) * 72 + kh + 8);
            #pragma unroll
            for (int nf = 0; nf < 8; nf++) {
                uint32_t bf[2];
                bf[0] = *(const uint32_t*)(sVts + (nf * 8 + p_) * 72 + kh);
                bf[1] = *(const uint32_t*)(sVts + (nf * 8 + p_) * 72 + kh + 8);
                mma_f16(O1[nf], a1f, bf);
                mma_f16(O2[nf], a2f, bf);
            }
        }
    }

    float rl10 = 1.f / l1[0], rl11 = 1.f / l1[1];
    float rl20 = 1.f / l2[0], rl21 = 1.f / l2[1];
    int row = q0 + wrow0 + p_;
    #pragma unroll
    for (int nf = 0; nf < 8; nf++) {
        int col = h * 64 + nf * 8 + 2 * q_;
        *(__half2*)(cat + (size_t)row * D2 + col)           = __floats2half2_rn(O1[nf][0] * rl10, O1[nf][1] * rl10);
        *(__half2*)(cat + (size_t)(row + 8) * D2 + col)     = __floats2half2_rn(O1[nf][2] * rl11, O1[nf][3] * rl11);
        *(__half2*)(cat + (size_t)row * D2 + D + col)       = __floats2half2_rn(O2[nf][0] * rl20, O2[nf][1] * rl20);
        *(__half2*)(cat + (size_t)(row + 8) * D2 + D + col) = __floats2half2_rn(O2[nf][2] * rl21, O2[nf][3] * rl21);
    }

    float tot = blockReduceSum(ssum);
    if (tid == 0) atomicAdd(&g_sigacc, (double)tot);
}

// ---------------- sigmoid sum over strictly-upper 128x128 tiles ----------------
__global__ __launch_bounds__(256) void k_sig_upper(const float* __restrict__ lm)
{
    int i = blockIdx.x, qi = 0, cnt = 15;
    while (i >= cnt) { i -= cnt; qi++; cnt--; }
    int cb = qi + 1 + i;
    int h = blockIdx.y;
    const float* base = lm + ((size_t)h * T + qi * 128) * T + cb * 128;

    float s = 0.f;
    int tr = threadIdx.x >> 5;
    int tc = (threadIdx.x & 31) * 4;
    #pragma unroll
    for (int rr = 0; rr < 16; rr++) {
        int row = tr * 16 + rr;
        float4 v = *(const float4*)(base + (size_t)row * T + tc);
        s += sigf(v.x) + sigf(v.y) + sigf(v.z) + sigf(v.w);
    }
    float tot = blockReduceSum(s);
    if (threadIdx.x == 0) atomicAdd(&g_sigacc, (double)tot);
}

__global__ void k_zero_acc() { g_sigacc = 0.0; }

__global__ void k_write_sp(float* out, int out_size)
{
    const long long TD = (long long)T * D;
    if (out_size > TD) {
        double mean = g_sigacc / ((double)H * (double)T * (double)T);
        out[TD] = (float)(SPARSITY_LAMBDA * mean);
    }
}

// ---------------- launch ----------------
#define FL_SMEM 180224

extern "C" void kernel_launch(void* const* d_in, const int* in_sizes, int n_in,
                              void* d_out, int out_size)
{
    const float* x      = (const float*)d_in[0];
    const float* W_qkv  = (const float*)d_in[2];
    const float* W_out  = (const float*)d_in[3];
    const float* logm   = (const float*)d_in[4];
    const float* W_gate = (const float*)d_in[5];
    const float* b_gate = (const float*)d_in[6];
    const float* g1     = (const float*)d_in[7];
    const float* b1     = (const float*)d_in[8];
    const float* g2     = (const float*)d_in[9];
    const float* b2     = (const float*)d_in[10];
    const float* W_ff1  = (const float*)d_in[11];
    const float* b_ff1  = (const float*)d_in[12];
    const float* W_ff2  = (const float*)d_in[13];
    const float* b_ff2  = (const float*)d_in[14];
    float* out = (float*)d_out;

    __half *xnh, *qkvh, *cath, *tmph, *hnh, *ffh;
    __half *wqkvh, *wgateh, *wouth, *wff1h, *wff2h;
    float *hbuf;
    cudaGetSymbolAddress((void**)&xnh,   g_xnh);
    cudaGetSymbolAddress((void**)&qkvh,  g_qkvh);
    cudaGetSymbolAddress((void**)&cath,  g_cath);
    cudaGetSymbolAddress((void**)&tmph,  g_tmph);
    cudaGetSymbolAddress((void**)&hbuf,  g_h);
    cudaGetSymbolAddress((void**)&hnh,   g_hnh);
    cudaGetSymbolAddress((void**)&ffh,   g_ffh);
    cudaGetSymbolAddress((void**)&wqkvh, g_wqkvh);
    cudaGetSymbolAddress((void**)&wgateh, g_wgateh);
    cudaGetSymbolAddress((void**)&wouth, g_wouth);
    cudaGetSymbolAddress((void**)&wff1h, g_wff1h);
    cudaGetSymbolAddress((void**)&wff2h, g_wff2h);

    cudaFuncSetAttribute(k_hgemm_nt<false, false, false, true >, cudaFuncAttributeMaxDynamicSharedMemorySize, HT_SMEM);
    cudaFuncSetAttribute(k_hgemm_nt<false, true,  false, true >, cudaFuncAttributeMaxDynamicSharedMemorySize, HT_SMEM);
    cudaFuncSetAttribute(k_hgemm_nt<false, false, true,  false>, cudaFuncAttributeMaxDynamicSharedMemorySize, HT_SMEM);
    cudaFuncSetAttribute(k_hgemm_nt<true,  true,  false, true >, cudaFuncAttributeMaxDynamicSharedMemorySize, HT_SMEM);
    cudaFuncSetAttribute(k_hgemm_nt<false, true,  true,  false>, cudaFuncAttributeMaxDynamicSharedMemorySize, HT_SMEM);
    cudaFuncSetAttribute(k_flash, cudaFuncAttributeMaxDynamicSharedMemorySize, FL_SMEM);

    k_zero_acc<<<1, 1>>>();

    // all weight conversions in one launch
    k_f2h_all<<<1184, 256>>>(W_qkv, W_gate, W_out, W_ff1, W_ff2,
                             wqkvh, wgateh, wouth, wff1h, wff2h);

    // ln1 -> half
    k_layernorm_h<<<T, 256>>>(x, g1, b1, xnh);

    // qkv = xn @ W_qkv^T (half out)
    k_hgemm_nt<false, false, false, true><<<dim3(D3 / 128, T / 128), 512, HT_SMEM>>>(
        xnh, D, wqkvh, D, qkvh, D3, D, nullptr, nullptr, 0);

    // strictly-upper sigmoid sum (causal part accumulated inside flash)
    k_sig_upper<<<dim3(120, H), 256>>>(logm);

    // fused dual-softmax attention -> cat (half) + causal sigmoid sum
    k_flash<<<256, 256, FL_SMEM>>>(qkvh, logm, cath);

    // tmp = cat @ W_gate^T + b_gate  (half out)
    k_hgemm_nt<false, true, false, true><<<dim3(D / 128, T / 128), 512, HT_SMEM>>>(
        cath, D2, wgateh, D2, tmph, D, D2, b_gate, nullptr, 0);

    // h = x + tmp @ W_out^T  (fp32 out)
    k_hgemm_nt<false, false, true, false><<<dim3(D / 128, T / 128), 512, HT_SMEM>>>(
        tmph, D, wouth, D, hbuf, D, D, nullptr, x, D);

    // ln2 -> half
    k_layernorm_h<<<T, 256>>>(hbuf, g2, b2, hnh);

    // ff = gelu(hn @ W_ff1^T + b_ff1)  (half out)
    k_hgemm_nt<true, true, false, true><<<dim3(DFF / 128, T / 128), 512, HT_SMEM>>>(
        hnh, D, wff1h, D, ffh, DFF, D, b_ff1, nullptr, 0);

    // out = h + ff @ W_ff2^T + b_ff2  (fp32 out)
    k_hgemm_nt<false, true, true, false><<<dim3(D / 128, T / 128), 512, HT_SMEM>>>(
        ffh, DFF, wff2h, DFF, out, D, DFF, b_ff2, hbuf, D);

    k_write_sp<<<1, 1>>>(out, out_size);
}

// round 16
// speedup vs baseline: 1.1187x; 1.0139x over previous
#include <cuda_runtime.h>
#include <cuda_fp16.h>
#include <math_constants.h>
#include <cstdint>

#define T 2048
#define D 1024
#define H 16
#define DH 64
#define D3 3072
#define D2 2048
#define DFF 4096
#define LN_EPS 1e-5f
#define SPARSITY_LAMBDA 0.0005f

// ---------------- scratch ----------------
__device__ __half g_xnh[(size_t)T * D];
__device__ __half g_qkvh[(size_t)T * D3];
__device__ __half g_cath[(size_t)T * D2];
__device__ __half g_tmph[(size_t)T * D];
__device__ float  g_h[(size_t)T * D];
__device__ __half g_hnh[(size_t)T * D];
__device__ __half g_ffh[(size_t)T * DFF];
__device__ __half g_wqkvh[(size_t)D3 * D];
__device__ __half g_wgateh[(size_t)D * D2];
__device__ __half g_wouth[(size_t)D * D];
__device__ __half g_wff1h[(size_t)DFF * D];
__device__ __half g_wff2h[(size_t)D * DFF];
__device__ double g_sigacc;

// ---------------- helpers ----------------
__device__ __forceinline__ void mma_f16(float (&d)[4], const uint32_t (&a)[4], const uint32_t (&b)[2]) {
    asm volatile(
        "mma.sync.aligned.m16n8k16.row.col.f32.f16.f16.f32 "
        "{%0,%1,%2,%3}, {%4,%5,%6,%7}, {%8,%9}, {%0,%1,%2,%3};\n"
        : "+f"(d[0]), "+f"(d[1]), "+f"(d[2]), "+f"(d[3])
        : "r"(a[0]), "r"(a[1]), "r"(a[2]), "r"(a[3]), "r"(b[0]), "r"(b[1]));
}

__device__ __forceinline__ void cp16(void* sdst, const void* gsrc) {
    uint32_t s = (uint32_t)__cvta_generic_to_shared(sdst);
    asm volatile("cp.async.cg.shared.global [%0], [%1], 16;" :: "r"(s), "l"(gsrc));
}
__device__ __forceinline__ void cp_commit() { asm volatile("cp.async.commit_group;"); }
template<int N> __device__ __forceinline__ void cp_wait() {
    asm volatile("cp.async.wait_group %0;" :: "n"(N));
}

__device__ __forceinline__ float sigf(float x) { return 1.f / (1.f + __expf(-x)); }

__device__ __forceinline__ float blockReduceSum(float v) {
    __shared__ float red[32];
    int lane = threadIdx.x & 31, wid = threadIdx.x >> 5;
    #pragma unroll
    for (int o = 16; o > 0; o >>= 1) v += __shfl_xor_sync(0xffffffff, v, o);
    __syncthreads();
    if (lane == 0) red[wid] = v;
    __syncthreads();
    int nw = (blockDim.x + 31) >> 5;
    float r = (threadIdx.x < nw) ? red[threadIdx.x] : 0.f;
    if (wid == 0) {
        #pragma unroll
        for (int o = 16; o > 0; o >>= 1) r += __shfl_xor_sync(0xffffffff, r, o);
        if (lane == 0) red[0] = r;
    }
    __syncthreads();
    return red[0];
}

// ---------------- merged fp32 -> fp16 conversion for all 5 weights ----------------
#define N4_QKV  786432
#define N4_GATE 524288
#define N4_OUT  262144
#define N4_FF1  1048576
#define N4_FF2  1048576
#define N4_TOT  (N4_QKV + N4_GATE + N4_OUT + N4_FF1 + N4_FF2)

__global__ __launch_bounds__(256) void k_f2h_all(
    const float* __restrict__ wqkv, const float* __restrict__ wgate,
    const float* __restrict__ wout, const float* __restrict__ wff1,
    const float* __restrict__ wff2,
    __half* __restrict__ hqkv, __half* __restrict__ hgate,
    __half* __restrict__ hout, __half* __restrict__ hff1,
    __half* __restrict__ hff2)
{
    for (int i = blockIdx.x * 256 + threadIdx.x; i < N4_TOT; i += gridDim.x * 256) {
        const float* src; __half* dst; int off;
        if (i < N4_QKV)                         { src = wqkv;  dst = hqkv;  off = i; }
        else if (i < N4_QKV + N4_GATE)          { src = wgate; dst = hgate; off = i - N4_QKV; }
        else if (i < N4_QKV + N4_GATE + N4_OUT) { src = wout;  dst = hout;  off = i - N4_QKV - N4_GATE; }
        else if (i < N4_QKV + N4_GATE + N4_OUT + N4_FF1)
                                                { src = wff1;  dst = hff1;  off = i - N4_QKV - N4_GATE - N4_OUT; }
        else                                    { src = wff2;  dst = hff2;  off = i - N4_QKV - N4_GATE - N4_OUT - N4_FF1; }
        float4 v = *(const float4*)(src + (size_t)off * 4);
        __half2* o = (__half2*)(dst + (size_t)off * 4);
        o[0] = __floats2half2_rn(v.x, v.y);
        o[1] = __floats2half2_rn(v.z, v.w);
    }
}

// ---------------- layernorm (half output) ----------------
__global__ __launch_bounds__(256) void k_layernorm_h(
    const float* __restrict__ x, const float* __restrict__ g,
    const float* __restrict__ b, __half* __restrict__ out)
{
    int t = blockIdx.x;
    const float* xr = x + (size_t)t * D;
    float s = 0.f, s2 = 0.f;
    for (int i = threadIdx.x; i < D; i += 256) {
        float v = xr[i];
        s += v; s2 += v * v;
    }
    float tot = blockReduceSum(s);
    float tot2 = blockReduceSum(s2);
    float mean = tot * (1.f / D);
    float var = tot2 * (1.f / D) - mean * mean;
    float rstd = rsqrtf(var + LN_EPS);
    __half* orow = out + (size_t)t * D;
    for (int i = threadIdx.x; i < D; i += 256) {
        orow[i] = __float2half((xr[i] - mean) * rstd * g[i] + b[i]);
    }
}

// ---------------- FP16 GEMM NT, 512 threads, 32x32 warp tiles, 3-stage cp.async ----------------
#define HT_PITCH 40
#define HT_STAGE (128 * HT_PITCH)
#define HT_SMEM (6 * HT_STAGE * sizeof(__half))  // 61440
template<bool GELU, bool HASBIAS, bool HASRES, bool HALFOUT>
__global__ __launch_bounds__(512, 2) void k_hgemm_nt(
    const __half* __restrict__ A, int lda,
    const __half* __restrict__ B, int ldb,
    void* __restrict__ Cv, int ldc,
    int K,
    const float* __restrict__ bias,
    const float* __restrict__ res, int ldres)
{
    int m0 = blockIdx.y * 128, n0 = blockIdx.x * 128;
    A += (size_t)m0 * lda;
    B += (size_t)n0 * ldb;

    extern __shared__ __half smh[];
    __half* Abuf = smh;
    __half* Bbuf = smh + 3 * HT_STAGE;

    int tid = threadIdx.x, lane = tid & 31, warp = tid >> 5;
    int wm = (warp & 3) * 32, wn = (warp >> 2) * 32;
    int lr = tid >> 2, lc = (tid & 3) * 8;

    float acc[2][4][4] = {};

    auto load = [&](int st, int k0) {
        __half* As_ = Abuf + st * HT_STAGE;
        __half* Bs_ = Bbuf + st * HT_STAGE;
        cp16(As_ + lr * HT_PITCH + lc, A + (size_t)lr * lda + k0 + lc);
        cp16(Bs_ + lr * HT_PITCH + lc, B + (size_t)lr * ldb + k0 + lc);
    };

    int nk = K / 32;
    load(0, 0); cp_commit();
    load(1, 32); cp_commit();

    for (int i = 0; i < nk; i++) {
        if (i + 1 < nk) cp_wait<1>(); else cp_wait<0>();
        __syncthreads();
        if (i + 2 < nk) { load((i + 2) % 3, (i + 2) * 32); cp_commit(); }

        const __half* As_ = Abuf + (i % 3) * HT_STAGE;
        const __half* Bs_ = Bbuf + (i % 3) * HT_STAGE;
        #pragma unroll
        for (int ks = 0; ks < 2; ks++) {
            int kh = ks * 16 + (lane & 3) * 2;
            uint32_t af[2][4], bf[4][2];
            #pragma unroll
            for (int mf = 0; mf < 2; mf++) {
                int r = wm + mf * 16 + (lane >> 2);
                af[mf][0] = *(const uint32_t*)(As_ + r * HT_PITCH + kh);
                af[mf][1] = *(const uint32_t*)(As_ + (r + 8) * HT_PITCH + kh);
                af[mf][2] = *(const uint32_t*)(As_ + r * HT_PITCH + kh + 8);
                af[mf][3] = *(const uint32_t*)(As_ + (r + 8) * HT_PITCH + kh + 8);
            }
            #pragma unroll
            for (int nf = 0; nf < 4; nf++) {
                int n = wn + nf * 8 + (lane >> 2);
                bf[nf][0] = *(const uint32_t*)(Bs_ + n * HT_PITCH + kh);
                bf[nf][1] = *(const uint32_t*)(Bs_ + n * HT_PITCH + kh + 8);
            }
            #pragma unroll
            for (int mf = 0; mf < 2; mf++)
                #pragma unroll
                for (int nf = 0; nf < 4; nf++)
                    mma_f16(acc[mf][nf], af[mf], bf[nf]);
        }
        __syncthreads();
    }

    #pragma unroll
    for (int mf = 0; mf < 2; mf++) {
        int row = m0 + wm + mf * 16 + (lane >> 2);
        #pragma unroll
        for (int nf = 0; nf < 4; nf++) {
            int col = n0 + wn + nf * 8 + 2 * (lane & 3);
            #pragma unroll
            for (int half_ = 0; half_ < 2; half_++) {
                int r = row + half_ * 8;
                float v0 = acc[mf][nf][half_ * 2 + 0];
                float v1 = acc[mf][nf][half_ * 2 + 1];
                if (HASBIAS) { v0 += bias[col]; v1 += bias[col + 1]; }
                if (GELU) {
                    v0 = 0.5f * v0 * (1.f + erff(v0 * 0.70710678118654752f));
                    v1 = 0.5f * v1 * (1.f + erff(v1 * 0.70710678118654752f));
                }
                if (HASRES) {
                    v0 += res[(size_t)r * ldres + col];
                    v1 += res[(size_t)r * ldres + col + 1];
                }
                if (HALFOUT) {
                    *(__half2*)((__half*)Cv + (size_t)r * ldc + col) = __floats2half2_rn(v0, v1);
                } else {
                    float2 o = {v0, v1};
                    *(float2*)((float*)Cv + (size_t)r * ldc + col) = o;
                }
            }
        }
    }
}

// ---------------- fused dual-softmax flash attention, 64-row CTAs (2/SM) ----------------
#define FL_SMEM 108544
__global__ __launch_bounds__(128) void k_flash(
    const __half* __restrict__ qkv, const float* __restrict__ logm,
    __half* __restrict__ cat)
{
    extern __shared__ char smraw[];
    __half* sQh = (__half*)smraw;
    __half* sKh = (__half*)(smraw + 9216);
    __half* sVn = (__half*)(smraw + 27648);
    __half* sVt = (__half*)(smraw + 46080);
    __half* sP  = (__half*)(smraw + 55296);
    float*  sM  = (float*)(smraw + 73728);

    int bid = blockIdx.x;
    int qb = 31 - (bid >> 4);    // heavy 64-row blocks first
    int h  = bid & 15;
    int q0 = qb * 64;
    int nkb = qb + 1;

    int tid = threadIdx.x, lane = tid & 31, warp = tid >> 5;
    int p_ = lane >> 2, q_ = lane & 3;
    int wrow0 = warp * 16;

    #pragma unroll
    for (int i = 0; i < 4; i++) {
        int idx = tid + i * 128;
        int row = idx >> 3, ch = (idx & 7) * 8;
        cp16(sQh + row * 72 + ch, qkv + (size_t)(q0 + row) * D3 + h * 64 + ch);
        cp16(sKh + row * 72 + ch, qkv + (size_t)row * D3 + D + h * 64 + ch);
        cp16(sVn + row * 72 + ch, qkv + (size_t)row * D3 + 2 * D + h * 64 + ch);
    }
    #pragma unroll
    for (int i = 0; i < 8; i++) {
        int idx = tid + i * 128;
        int row = idx >> 4, c4 = (idx & 15) * 4;
        cp16(sM + row * 68 + c4, logm + ((size_t)h * T + q0 + row) * T + c4);
    }
    cp_commit();

    float O1[8][4] = {}, O2[8][4] = {};
    float m1[2] = {-1e30f, -1e30f}, l1[2] = {0.f, 0.f};
    float m2[2] = {-1e30f, -1e30f}, l2[2] = {0.f, 0.f};
    float ssum = 0.f;

    int r0 = wrow0 + p_;
    int t0 = q0 + r0, t1 = t0 + 8;
    __half* sP1 = sP + warp * 1152;
    __half* sP2 = sP + 4608 + warp * 1152;

    int vdh = tid & 63;
    int vtb = (tid >> 6) * 32;

    for (int j = 0; j < nkb; j++) {
        int st = j & 1;
        int kb0 = j * 64;
        cp_wait<0>();
        __syncthreads();
        if (j + 1 < nkb) {
            int st2 = st ^ 1, kb2 = kb0 + 64;
            __half* dK = sKh + st2 * 4608;
            __half* dV = sVn + st2 * 4608;
            float*  dM = sM  + st2 * 4352;
            #pragma unroll
            for (int i = 0; i < 4; i++) {
                int idx = tid + i * 128;
                int row = idx >> 3, ch = (idx & 7) * 8;
                cp16(dK + row * 72 + ch, qkv + (size_t)(kb2 + row) * D3 + D + h * 64 + ch);
                cp16(dV + row * 72 + ch, qkv + (size_t)(kb2 + row) * D3 + 2 * D + h * 64 + ch);
            }
            #pragma unroll
            for (int i = 0; i < 8; i++) {
                int idx = tid + i * 128;
                int row = idx >> 4, c4 = (idx & 15) * 4;
                cp16(dM + row * 68 + c4, logm + ((size_t)h * T + q0 + row) * T + kb2 + c4);
            }
            cp_commit();
        }

        const __half* sKs = sKh + st * 4608;
        const __half* sVns = sVn + st * 4608;
        const float* sMs = sM + st * 4352;

        #pragma unroll
        for (int t2 = 0; t2 < 32; t2 += 2) {
            int tok = vtb + t2;
            __half a = sVns[tok * 72 + vdh];
            __half b = sVns[(tok + 1) * 72 + vdh];
            *(__half2*)(sVt + vdh * 72 + tok) = __halves2half2(a, b);
        }
        __syncthreads();

        float sg[8][4];
        #pragma unroll
        for (int nf = 0; nf < 8; nf++) {
            int c0 = nf * 8 + 2 * q_;
            float2 a = *(const float2*)(sMs + r0 * 68 + c0);
            float2 b = *(const float2*)(sMs + (r0 + 8) * 68 + c0);
            sg[nf][0] = sigf(a.x); sg[nf][1] = sigf(a.y);
            sg[nf][2] = sigf(b.x); sg[nf][3] = sigf(b.y);
            ssum += sg[nf][0] + sg[nf][1] + sg[nf][2] + sg[nf][3];
        }

        if (kb0 > q0 + wrow0 + 15) continue;

        float sc[8][4] = {};
        #pragma unroll
        for (int kc = 0; kc < 4; kc++) {
            int kh = kc * 16 + 2 * q_;
            uint32_t af[4];
            af[0] = *(const uint32_t*)(sQh + r0 * 72 + kh);
            af[1] = *(const uint32_t*)(sQh + (r0 + 8) * 72 + kh);
            af[2] = *(const uint32_t*)(sQh + r0 * 72 + kh + 8);
            af[3] = *(const uint32_t*)(sQh + (r0 + 8) * 72 + kh + 8);
            #pragma unroll
            for (int nf = 0; nf < 8; nf++) {
                uint32_t bf[2];
                bf[0] = *(const uint32_t*)(sKs + (nf * 8 + p_) * 72 + kh);
                bf[1] = *(const uint32_t*)(sKs + (nf * 8 + p_) * 72 + kh + 8);
                mma_f16(sc[nf], af, bf);
            }
        }
        #pragma unroll
        for (int nf = 0; nf < 8; nf++) {
            sc[nf][0] *= 0.125f; sc[nf][1] *= 0.125f;
            sc[nf][2] *= 0.125f; sc[nf][3] *= 0.125f;
        }

        #pragma unroll
        for (int br = 0; br < 2; br++) {
            float* mB = br ? m2 : m1;
            float* lB = br ? l2 : l1;
            float (*OB)[4] = br ? O2 : O1;
            __half* sPw = br ? sP2 : sP1;

            float v[8][4];
            float rmx0 = -1e30f, rmx1 = -1e30f;
            #pragma unroll
            for (int nf = 0; nf < 8; nf++) {
                int c0 = kb0 + nf * 8 + 2 * q_;
                float w0 = br ? sc[nf][0] * sg[nf][0] : sc[nf][0];
                float w1 = br ? sc[nf][1] * sg[nf][1] : sc[nf][1];
                float w2 = br ? sc[nf][2] * sg[nf][2] : sc[nf][2];
                float w3 = br ? sc[nf][3] * sg[nf][3] : sc[nf][3];
                v[nf][0] = (c0     <= t0) ? w0 : -1e30f;
                v[nf][1] = (c0 + 1 <= t0) ? w1 : -1e30f;
                v[nf][2] = (c0     <= t1) ? w2 : -1e30f;
                v[nf][3] = (c0 + 1 <= t1) ? w3 : -1e30f;
                rmx0 = fmaxf(rmx0, fmaxf(v[nf][0], v[nf][1]));
                rmx1 = fmaxf(rmx1, fmaxf(v[nf][2], v[nf][3]));
            }
            rmx0 = fmaxf(rmx0, __shfl_xor_sync(0xffffffff, rmx0, 1));
            rmx0 = fmaxf(rmx0, __shfl_xor_sync(0xffffffff, rmx0, 2));
            rmx1 = fmaxf(rmx1, __shfl_xor_sync(0xffffffff, rmx1, 1));
            rmx1 = fmaxf(rmx1, __shfl_xor_sync(0xffffffff, rmx1, 2));

            float mn0 = fmaxf(mB[0], rmx0), mn1 = fmaxf(mB[1], rmx1);
            float al0 = __expf(mB[0] - mn0), al1 = __expf(mB[1] - mn1);
            float rs0 = 0.f, rs1 = 0.f;
            #pragma unroll
            for (int nf = 0; nf < 8; nf++) {
                v[nf][0] = __expf(v[nf][0] - mn0);
                v[nf][1] = __expf(v[nf][1] - mn0);
                v[nf][2] = __expf(v[nf][2] - mn1);
                v[nf][3] = __expf(v[nf][3] - mn1);
                rs0 += v[nf][0] + v[nf][1];
                rs1 += v[nf][2] + v[nf][3];
            }
            rs0 += __shfl_xor_sync(0xffffffff, rs0, 1);
            rs0 += __shfl_xor_sync(0xffffffff, rs0, 2);
            rs1 += __shfl_xor_sync(0xffffffff, rs1, 1);
            rs1 += __shfl_xor_sync(0xffffffff, rs1, 2);
            lB[0] = lB[0] * al0 + rs0; lB[1] = lB[1] * al1 + rs1;
            mB[0] = mn0; mB[1] = mn1;

            #pragma unroll
            for (int nf = 0; nf < 8; nf++) {
                OB[nf][0] *= al0; OB[nf][1] *= al0;
                OB[nf][2] *= al1; OB[nf][3] *= al1;
                *(__half2*)(sPw + p_ * 72 + nf * 8 + 2 * q_)       = __floats2half2_rn(v[nf][0], v[nf][1]);
                *(__half2*)(sPw + (p_ + 8) * 72 + nf * 8 + 2 * q_) = __floats2half2_rn(v[nf][2], v[nf][3]);
            }
        }
        __syncwarp();

        #pragma unroll
        for (int kc = 0; kc < 4; kc++) {
            int kh = kc * 16 + 2 * q_;
            uint32_t a1f[4], a2f[4];
            a1f[0] = *(const uint32_t*)(sP1 + p_ * 72 + kh);
            a1f[1] = *(const uint32_t*)(sP1 + (p_ + 8) * 72 + kh);
            a1f[2] = *(const uint32_t*)(sP1 + p_ * 72 + kh + 8);
            a1f[3] = *(const uint32_t*)(sP1 + (p_ + 8) * 72 + kh + 8);
            a2f[0] = *(const uint32_t*)(sP2 + p_ * 72 + kh);
            a2f[1] = *(const uint32_t*)(sP2 + (p_ + 8) * 72 + kh);
            a2f[2] = *(const uint32_t*)(sP2 + p_ * 72 + kh + 8);
            a2f[3] = *(const uint32_t*)(sP2 + (p_ + 8) * 72 + kh + 8);
            #pragma unroll
            for (int nf = 0; nf < 8; nf++) {
                uint32_t bf[2];
                bf[0] = *(const uint32_t*)(sVt + (nf * 8 + p_) * 72 + kh);
                bf[1] = *(const uint32_t*)(sVt + (nf * 8 + p_) * 72 + kh + 8);
                mma_f16(O1[nf], a1f, bf);
                mma_f16(O2[nf], a2f, bf);
            }
        }
    }

    float rl10 = 1.f / l1[0], rl11 = 1.f / l1[1];
    float rl20 = 1.f / l2[0], rl21 = 1.f / l2[1];
    int row = q0 + wrow0 + p_;
    #pragma unroll
    for (int nf = 0; nf < 8; nf++) {
        int col = h * 64 + nf * 8 + 2 * q_;
        *(__half2*)(cat + (size_t)row * D2 + col)           = __floats2half2_rn(O1[nf][0] * rl10, O1[nf][1] * rl10);
        *(__half2*)(cat + (size_t)(row + 8) * D2 + col)     = __floats2half2_rn(O1[nf][2] * rl11, O1[nf][3] * rl11);
        *(__half2*)(cat + (size_t)row * D2 + D + col)       = __floats2half2_rn(O2[nf][0] * rl20, O2[nf][1] * rl20);
        *(__half2*)(cat + (size_t)(row + 8) * D2 + D + col) = __floats2half2_rn(O2[nf][2] * rl21, O2[nf][3] * rl21);
    }

    float tot = blockReduceSum(ssum);
    if (tid == 0) atomicAdd(&g_sigacc, (double)tot);
}

// ---------------- sigmoid sum over strictly-upper 64x64 tiles ----------------
// grid (496, H): (qb, cb) pairs with cb > qb, qb in 0..30 (64-granularity,
// matching the 64-row flash blocks' causal coverage).
__global__ __launch_bounds__(256) void k_sig_upper(const float* __restrict__ lm)
{
    int i = blockIdx.x, qb = 0, cnt = 31;
    while (i >= cnt) { i -= cnt; qb++; cnt--; }
    int cb = qb + 1 + i;
    int h = blockIdx.y;
    const float* base = lm + ((size_t)h * T + qb * 64) * T + cb * 64;

    float s = 0.f;
    int tr = (threadIdx.x >> 4) * 4;      // row group 0..60 step 4
    int tc = (threadIdx.x & 15) * 4;      // col 0..60
    #pragma unroll
    for (int rr = 0; rr < 4; rr++) {
        float4 v = *(const float4*)(base + (size_t)(tr + rr) * T + tc);
        s += sigf(v.x) + sigf(v.y) + sigf(v.z) + sigf(v.w);
    }
    float tot = blockReduceSum(s);
    if (threadIdx.x == 0) atomicAdd(&g_sigacc, (double)tot);
}

__global__ void k_zero_acc() { g_sigacc = 0.0; }

__global__ void k_write_sp(float* out, int out_size)
{
    const long long TD = (long long)T * D;
    if (out_size > TD) {
        double mean = g_sigacc / ((double)H * (double)T * (double)T);
        out[TD] = (float)(SPARSITY_LAMBDA * mean);
    }
}

// ---------------- launch ----------------
extern "C" void kernel_launch(void* const* d_in, const int* in_sizes, int n_in,
                              void* d_out, int out_size)
{
    const float* x      = (const float*)d_in[0];
    const float* W_qkv  = (const float*)d_in[2];
    const float* W_out  = (const float*)d_in[3];
    const float* logm   = (const float*)d_in[4];
    const float* W_gate = (const float*)d_in[5];
    const float* b_gate = (const float*)d_in[6];
    const float* g1     = (const float*)d_in[7];
    const float* b1     = (const float*)d_in[8];
    const float* g2     = (const float*)d_in[9];
    const float* b2     = (const float*)d_in[10];
    const float* W_ff1  = (const float*)d_in[11];
    const float* b_ff1  = (const float*)d_in[12];
    const float* W_ff2  = (const float*)d_in[13];
    const float* b_ff2  = (const float*)d_in[14];
    float* out = (float*)d_out;

    __half *xnh, *qkvh, *cath, *tmph, *hnh, *ffh;
    __half *wqkvh, *wgateh, *wouth, *wff1h, *wff2h;
    float *hbuf;
    cudaGetSymbolAddress((void**)&xnh,   g_xnh);
    cudaGetSymbolAddress((void**)&qkvh,  g_qkvh);
    cudaGetSymbolAddress((void**)&cath,  g_cath);
    cudaGetSymbolAddress((void**)&tmph,  g_tmph);
    cudaGetSymbolAddress((void**)&hbuf,  g_h);
    cudaGetSymbolAddress((void**)&hnh,   g_hnh);
    cudaGetSymbolAddress((void**)&ffh,   g_ffh);
    cudaGetSymbolAddress((void**)&wqkvh, g_wqkvh);
    cudaGetSymbolAddress((void**)&wgateh, g_wgateh);
    cudaGetSymbolAddress((void**)&wouth, g_wouth);
    cudaGetSymbolAddress((void**)&wff1h, g_wff1h);
    cudaGetSymbolAddress((void**)&wff2h, g_wff2h);

    cudaFuncSetAttribute(k_hgemm_nt<false, false, false, true >, cudaFuncAttributeMaxDynamicSharedMemorySize, HT_SMEM);
    cudaFuncSetAttribute(k_hgemm_nt<false, true,  false, true >, cudaFuncAttributeMaxDynamicSharedMemorySize, HT_SMEM);
    cudaFuncSetAttribute(k_hgemm_nt<false, false, true,  false>, cudaFuncAttributeMaxDynamicSharedMemorySize, HT_SMEM);
    cudaFuncSetAttribute(k_hgemm_nt<true,  true,  false, true >, cudaFuncAttributeMaxDynamicSharedMemorySize, HT_SMEM);
    cudaFuncSetAttribute(k_hgemm_nt<false, true,  true,  false>, cudaFuncAttributeMaxDynamicSharedMemorySize, HT_SMEM);
    cudaFuncSetAttribute(k_flash, cudaFuncAttributeMaxDynamicSharedMemorySize, FL_SMEM);

    k_zero_acc<<<1, 1>>>();

    // all weight conversions in one launch
    k_f2h_all<<<1184, 256>>>(W_qkv, W_gate, W_out, W_ff1, W_ff2,
                             wqkvh, wgateh, wouth, wff1h, wff2h);

    // ln1 -> half
    k_layernorm_h<<<T, 256>>>(x, g1, b1, xnh);

    // qkv = xn @ W_qkv^T (half out)
    k_hgemm_nt<false, false, false, true><<<dim3(D3 / 128, T / 128), 512, HT_SMEM>>>(
        xnh, D, wqkvh, D, qkvh, D3, D, nullptr, nullptr, 0);

    // strictly-upper sigmoid sum at 64-granularity (causal part inside flash)
    k_sig_upper<<<dim3(496, H), 256>>>(logm);

    // fused dual-softmax attention -> cat (half) + causal sigmoid sum (64-row CTAs)
    k_flash<<<512, 128, FL_SMEM>>>(qkvh, logm, cath);

    // tmp = cat @ W_gate^T + b_gate  (half out)
    k_hgemm_nt<false, true, false, true><<<dim3(D / 128, T / 128), 512, HT_SMEM>>>(
        cath, D2, wgateh, D2, tmph, D, D2, b_gate, nullptr, 0);

    // h = x + tmp @ W_out^T  (fp32 out)
    k_hgemm_nt<false, false, true, false><<<dim3(D / 128, T / 128), 512, HT_SMEM>>>(
        tmph, D, wouth, D, hbuf, D, D, nullptr, x, D);

    // ln2 -> half
    k_layernorm_h<<<T, 256>>>(hbuf, g2, b2, hnh);

    // ff = gelu(hn @ W_ff1^T + b_ff1)  (half out)
    k_hgemm_nt<true, true, false, true><<<dim3(DFF / 128, T / 128), 512, HT_SMEM>>>(
        hnh, D, wff1h, D, ffh, DFF, D, b_ff1, nullptr, 0);

    // out = h + ff @ W_ff2^T + b_ff2  (fp32 out)
    k_hgemm_nt<false, true, true, false><<<dim3(D / 128, T / 128), 512, HT_SMEM>>>(
        ffh, DFF, wff2h, DFF, out, D, DFF, b_ff2, hbuf, D);

    k_write_sp<<<1, 1>>>(out, out_size);
}